// round 1
// baseline (speedup 1.0000x reference)
#include <cuda_runtime.h>

#define NN 50000
#define NE 800000
#define NG 1024
#define DIN 9
#define DD 64

// ---- scratch (static device globals; no dynamic allocation allowed) ----
__device__ float    g_h  [NN*DD];   // layer activations (post-tanh)
__device__ float    g_hw [NN*DD];   // h @ W
__device__ float    g_acc[NN*DD];   // scatter accumulator (init = self-loop term)
__device__ float    g_deg[NN];
__device__ float    g_dinv[NN];
__device__ unsigned g_gmax[NG*DD];  // order-preserving uint-encoded float max
__device__ float    g_gsum[NG*DD];
__device__ float    g_gcnt[NG];

// ---- order-preserving float <-> uint encoding for atomicMax ----
__device__ __forceinline__ unsigned fkey(float f) {
    unsigned b = __float_as_uint(f);
    return (b & 0x80000000u) ? ~b : (b | 0x80000000u);
}
__device__ __forceinline__ float funkey(unsigned k) {
    unsigned b = (k & 0x80000000u) ? (k & 0x7FFFFFFFu) : ~k;
    return __uint_as_float(b);
}

__global__ void k_init() {
    int i = blockIdx.x * blockDim.x + threadIdx.x;
    if (i < NN) g_deg[i] = 1.0f;                 // self-loop
    if (i < NG*DD) { g_gmax[i] = 0u; g_gsum[i] = 0.0f; }
    if (i < NG) g_gcnt[i] = 0.0f;
}

__global__ void k_deg(const int* __restrict__ dst) {
    int e = blockIdx.x * blockDim.x + threadIdx.x;
    if (e < NE) atomicAdd(&g_deg[dst[e]], 1.0f);
}

__global__ void k_dinv() {
    int i = blockIdx.x * blockDim.x + threadIdx.x;
    if (i < NN) g_dinv[i] = rsqrtf(g_deg[i]);
}

// layer-0 GEMM: x[N,9] @ W0[9,64]; epilogue writes hw and acc = dinv^2 * hw (self-loop)
__global__ void k_gemm0(const float* __restrict__ x, const float* __restrict__ W) {
    __shared__ float Ws[DIN*DD];
    int tid = threadIdx.x;
    for (int i = tid; i < DIN*DD; i += 256) Ws[i] = W[i];
    __syncthreads();
    int ni = tid >> 6, j = tid & 63;
    int n = blockIdx.x * 4 + ni;
    if (n >= NN) return;
    float s = 0.0f;
    #pragma unroll
    for (int k = 0; k < DIN; k++) s += x[n*DIN + k] * Ws[k*DD + j];
    float d = g_dinv[n];
    g_hw [n*DD + j] = s;
    g_acc[n*DD + j] = d * d * s;
}

// 64x64 GEMM for layers 1-3: g_h[N,64] @ W[64,64]; same epilogue
__global__ void k_gemm64(const float* __restrict__ W) {
    __shared__ float Ws[DD*DD];
    __shared__ float hs[4][DD];
    int tid = threadIdx.x;
    #pragma unroll
    for (int i = 0; i < 16; i++) Ws[tid + i*256] = W[tid + i*256];
    int r = tid >> 6, c = tid & 63;
    int n = blockIdx.x * 4 + r;
    hs[r][c] = (n < NN) ? g_h[n*DD + c] : 0.0f;
    __syncthreads();
    if (n >= NN) return;
    float s = 0.0f;
    #pragma unroll
    for (int k = 0; k < DD; k++) s += hs[r][k] * Ws[k*DD + c];
    float d = g_dinv[n];
    g_hw [n*DD + c] = s;
    g_acc[n*DD + c] = d * d * s;
}

// edge scatter: 16 threads per edge, float4 per thread (coalesced 256B gather/edge)
__global__ void k_scatter(const int* __restrict__ src, const int* __restrict__ dst) {
    int t = blockIdx.x * blockDim.x + threadIdx.x;
    int e = t >> 4, c = t & 15;
    if (e >= NE) return;
    int r  = src[e];
    int cl = dst[e];
    float nrm = g_dinv[r] * g_dinv[cl];
    float4 v = reinterpret_cast<const float4*>(g_hw)[r*16 + c];
    float* p = &g_acc[cl*DD + c*4];
    atomicAdd(p + 0, nrm * v.x);
    atomicAdd(p + 1, nrm * v.y);
    atomicAdd(p + 2, nrm * v.z);
    atomicAdd(p + 3, nrm * v.w);
}

__global__ void k_bias_tanh(const float* __restrict__ b) {
    int i = blockIdx.x * blockDim.x + threadIdx.x;
    if (i < NN*DD) g_h[i] = tanhf(g_acc[i] + b[i & 63]);
}

__global__ void k_pool(const int* __restrict__ batch) {
    int t = blockIdx.x * blockDim.x + threadIdx.x;
    if (t >= NN*DD) return;
    int n = t >> 6, j = t & 63;
    int g = batch[n];
    float v = g_h[t];
    atomicMax(&g_gmax[g*DD + j], fkey(v));
    atomicAdd(&g_gsum[g*DD + j], v);
    if (j == 0) atomicAdd(&g_gcnt[g], 1.0f);
}

__global__ void k_out(const float* __restrict__ Wout, const float* __restrict__ bout,
                      float* __restrict__ out) {
    int g = blockIdx.x * blockDim.x + threadIdx.x;
    if (g >= NG) return;
    float cnt = fmaxf(g_gcnt[g], 1.0f);
    float s = bout[0];
    #pragma unroll
    for (int d = 0; d < DD; d++) {
        float mx = funkey(g_gmax[g*DD + d]);
        float mn = g_gsum[g*DD + d] / cnt;
        s += mx * Wout[d] + mn * Wout[DD + d];
    }
    out[g] = s;
}

extern "C" void kernel_launch(void* const* d_in, const int* in_sizes, int n_in,
                              void* d_out, int out_size) {
    const float* x     = (const float*)d_in[0];
    const int*   eidx  = (const int*)  d_in[1];
    const int*   batch = (const int*)  d_in[2];
    const float* W0 = (const float*)d_in[3];  const float* b0 = (const float*)d_in[4];
    const float* W1 = (const float*)d_in[5];  const float* b1 = (const float*)d_in[6];
    const float* W2 = (const float*)d_in[7];  const float* b2 = (const float*)d_in[8];
    const float* W3 = (const float*)d_in[9];  const float* b3 = (const float*)d_in[10];
    const float* Wout = (const float*)d_in[11];
    const float* bout = (const float*)d_in[12];
    float* out = (float*)d_out;

    const int* src = eidx;       // edge_index[0]
    const int* dst = eidx + NE;  // edge_index[1]

    k_init<<<(NG*DD + 255) / 256, 256>>>();
    k_deg <<<(NE + 255) / 256, 256>>>(dst);
    k_dinv<<<(NN + 255) / 256, 256>>>();

    const int gemm_blocks = (NN + 3) / 4;          // 12500
    const int scat_blocks = (NE * 16 + 255) / 256; // 50000
    const int nd_blocks   = (NN * DD + 255) / 256; // 12500

    // layer 0
    k_gemm0<<<gemm_blocks, 256>>>(x, W0);
    k_scatter<<<scat_blocks, 256>>>(src, dst);
    k_bias_tanh<<<nd_blocks, 256>>>(b0);
    // layers 1-3
    const float* Ws[3] = {W1, W2, W3};
    const float* bs[3] = {b1, b2, b3};
    for (int l = 0; l < 3; l++) {
        k_gemm64<<<gemm_blocks, 256>>>(Ws[l]);
        k_scatter<<<scat_blocks, 256>>>(src, dst);
        k_bias_tanh<<<nd_blocks, 256>>>(bs[l]);
    }

    k_pool<<<nd_blocks, 256>>>(batch);
    k_out<<<(NG + 255) / 256, 256>>>(Wout, bout, out);
}

// round 3
// speedup vs baseline: 2.1837x; 2.1837x over previous
#include <cuda_runtime.h>

#define NN 50000
#define NE 800000
#define NG 1024
#define DIN 9
#define DD 64
#define SCAN_BLKS ((NN + 255) / 256)   // 196

// ---- scratch (static device globals) ----
__device__ float    g_h   [NN*DD];    // activations (post-tanh)
__device__ float    g_hw  [NN*DD];    // h @ W
__device__ float    g_aggx[NN*DIN];   // aggregated raw features (layer 0)
__device__ int      g_degi[NN];       // in-degree (no self loop)
__device__ float    g_dinv[NN];
__device__ int      g_rp  [NN];       // CSR row start
__device__ int      g_cur [NN];       // fill cursor
__device__ int2     g_ep  [NE];       // (src, bitcast norm)
__device__ int      g_bsum[256];
__device__ unsigned g_gmax[NG*DD];
__device__ float    g_gsum[NG*DD];
__device__ float    g_gcnt[NG];

__device__ __forceinline__ unsigned fkey(float f) {
    unsigned b = __float_as_uint(f);
    return (b & 0x80000000u) ? ~b : (b | 0x80000000u);
}
__device__ __forceinline__ float funkey(unsigned k) {
    unsigned b = (k & 0x80000000u) ? (k & 0x7FFFFFFFu) : ~k;
    return __uint_as_float(b);
}

__global__ void k_init() {
    int i = blockIdx.x * blockDim.x + threadIdx.x;
    if (i < NN) g_degi[i] = 0;
    if (i < NG*DD) { g_gmax[i] = 0u; g_gsum[i] = 0.0f; }
    if (i < NG) g_gcnt[i] = 0.0f;
}

__global__ void k_deg(const int* __restrict__ dst) {
    int e = blockIdx.x * blockDim.x + threadIdx.x;
    if (e < NE) atomicAdd(&g_degi[dst[e]], 1);
}

// exclusive scan, stage 1: per-block scan + block sums
__global__ void k_scan1() {
    __shared__ int sh[256];
    int t = threadIdx.x, i = blockIdx.x * 256 + t;
    int v = (i < NN) ? g_degi[i] : 0;
    sh[t] = v; __syncthreads();
    #pragma unroll
    for (int off = 1; off < 256; off <<= 1) {
        int u = (t >= off) ? sh[t - off] : 0;
        __syncthreads();
        sh[t] += u; __syncthreads();
    }
    if (i < NN) g_rp[i] = sh[t] - v;
    if (t == 255) g_bsum[blockIdx.x] = sh[255];
}

__global__ void k_scan2() {
    __shared__ int sh[256];
    int t = threadIdx.x;
    int v = (t < SCAN_BLKS) ? g_bsum[t] : 0;
    sh[t] = v; __syncthreads();
    #pragma unroll
    for (int off = 1; off < 256; off <<= 1) {
        int u = (t >= off) ? sh[t - off] : 0;
        __syncthreads();
        sh[t] += u; __syncthreads();
    }
    g_bsum[t] = sh[t] - v;
}

__global__ void k_scan3() {
    int i = blockIdx.x * blockDim.x + threadIdx.x;
    if (i >= NN) return;
    g_rp[i] += g_bsum[i >> 8];
    g_cur[i] = 0;
    g_dinv[i] = rsqrtf(1.0f + (float)g_degi[i]);
}

__global__ void k_fill(const int* __restrict__ src, const int* __restrict__ dst) {
    int e = blockIdx.x * blockDim.x + threadIdx.x;
    if (e >= NE) return;
    int d = dst[e], s = src[e];
    int pos = g_rp[d] + atomicAdd(&g_cur[d], 1);
    g_ep[pos] = make_int2(s, __float_as_int(g_dinv[s] * g_dinv[d]));
}

// layer-0 aggregation over raw features: aggx = D^-1/2 (A+I) D^-1/2 x  (9 dims)
__global__ void k_gather9(const float* __restrict__ x) {
    int t = blockIdx.x * blockDim.x + threadIdx.x;
    int n = t >> 4, c = t & 15;
    if (n >= NN || c >= DIN) return;
    int rp = g_rp[n], dg = g_degi[n];
    float dn = g_dinv[n];
    float acc = dn * dn * x[n*DIN + c];
    for (int j = 0; j < dg; j++) {
        int2 p = g_ep[rp + j];
        acc += __int_as_float(p.y) * x[p.x*DIN + c];
    }
    g_aggx[n*DIN + c] = acc;
}

// h0 = tanh(aggx @ W0 + b0)
__global__ void k_gemm0f(const float* __restrict__ W, const float* __restrict__ b) {
    __shared__ float Ws[DIN*DD];
    __shared__ float hs[4][12];
    int tid = threadIdx.x;
    for (int i = tid; i < DIN*DD; i += 256) Ws[i] = W[i];
    int nb = blockIdx.x * 4;
    if (tid < 36) {
        int r = tid / DIN, k = tid % DIN, n = nb + r;
        hs[r][k] = (n < NN) ? g_aggx[n*DIN + k] : 0.0f;
    }
    __syncthreads();
    int r = tid >> 6, j = tid & 63;
    int n = nb + r;
    if (n >= NN) return;
    float s = b[j];
    #pragma unroll
    for (int k = 0; k < DIN; k++) s += hs[r][k] * Ws[k*DD + j];
    g_h[n*DD + j] = tanhf(s);
}

// 64x64 GEMM: g_hw = g_h @ W
__global__ void k_gemm64(const float* __restrict__ W) {
    __shared__ float Ws[DD*DD];
    __shared__ float hs[4][DD];
    int tid = threadIdx.x;
    #pragma unroll
    for (int i = 0; i < 16; i++) Ws[tid + i*256] = W[tid + i*256];
    int r = tid >> 6, c = tid & 63;
    int n = blockIdx.x * 4 + r;
    hs[r][c] = (n < NN) ? g_h[n*DD + c] : 0.0f;
    __syncthreads();
    if (n >= NN) return;
    float s = 0.0f;
    #pragma unroll
    for (int k = 0; k < DD; k++) s += hs[r][k] * Ws[k*DD + c];
    g_hw[n*DD + c] = s;
}

// CSR gather + self-loop + bias + tanh (+ optional fused pooling)
template <bool POOL>
__global__ void k_gather64(const float* __restrict__ b, const int* __restrict__ batch) {
    int t = blockIdx.x * blockDim.x + threadIdx.x;
    int n = t >> 4, c = t & 15;
    if (n >= NN) return;
    int rp = g_rp[n], dg = g_degi[n];
    float dn = g_dinv[n];
    const float4* hw4 = reinterpret_cast<const float4*>(g_hw);
    float4 self = hw4[n*16 + c];
    float d2 = dn * dn;
    float4 a0 = make_float4(d2*self.x, d2*self.y, d2*self.z, d2*self.w);
    float4 a1 = make_float4(0.f, 0.f, 0.f, 0.f);
    int j = 0;
    // 2-way pipelined: two independent load chains
    for (; j + 1 < dg; j += 2) {
        int2 p0 = g_ep[rp + j];
        int2 p1 = g_ep[rp + j + 1];
        float4 v0 = hw4[p0.x*16 + c];
        float4 v1 = hw4[p1.x*16 + c];
        float w0 = __int_as_float(p0.y), w1 = __int_as_float(p1.y);
        a0.x += w0*v0.x; a0.y += w0*v0.y; a0.z += w0*v0.z; a0.w += w0*v0.w;
        a1.x += w1*v1.x; a1.y += w1*v1.y; a1.z += w1*v1.z; a1.w += w1*v1.w;
    }
    if (j < dg) {
        int2 p0 = g_ep[rp + j];
        float4 v0 = hw4[p0.x*16 + c];
        float w0 = __int_as_float(p0.y);
        a0.x += w0*v0.x; a0.y += w0*v0.y; a0.z += w0*v0.z; a0.w += w0*v0.w;
    }
    float4 bb = reinterpret_cast<const float4*>(b)[c];
    float4 r;
    r.x = tanhf(a0.x + a1.x + bb.x);
    r.y = tanhf(a0.y + a1.y + bb.y);
    r.z = tanhf(a0.z + a1.z + bb.z);
    r.w = tanhf(a0.w + a1.w + bb.w);
    reinterpret_cast<float4*>(g_h)[n*16 + c] = r;
    if (POOL) {
        int g = batch[n];
        int base = g*DD + c*4;
        atomicMax(&g_gmax[base + 0], fkey(r.x));
        atomicMax(&g_gmax[base + 1], fkey(r.y));
        atomicMax(&g_gmax[base + 2], fkey(r.z));
        atomicMax(&g_gmax[base + 3], fkey(r.w));
        atomicAdd(&g_gsum[base + 0], r.x);
        atomicAdd(&g_gsum[base + 1], r.y);
        atomicAdd(&g_gsum[base + 2], r.z);
        atomicAdd(&g_gsum[base + 3], r.w);
        if (c == 0) atomicAdd(&g_gcnt[g], 1.0f);
    }
}

__global__ void k_out(const float* __restrict__ Wout, const float* __restrict__ bout,
                      float* __restrict__ out) {
    int g = blockIdx.x * blockDim.x + threadIdx.x;
    if (g >= NG) return;
    float cnt = fmaxf(g_gcnt[g], 1.0f);
    float s = bout[0];
    #pragma unroll
    for (int d = 0; d < DD; d++) {
        s += funkey(g_gmax[g*DD + d]) * Wout[d]
           + (g_gsum[g*DD + d] / cnt) * Wout[DD + d];
    }
    out[g] = s;
}

extern "C" void kernel_launch(void* const* d_in, const int* in_sizes, int n_in,
                              void* d_out, int out_size) {
    const float* x     = (const float*)d_in[0];
    const int*   eidx  = (const int*)  d_in[1];
    const int*   batch = (const int*)  d_in[2];
    const float* W0 = (const float*)d_in[3];  const float* b0 = (const float*)d_in[4];
    const float* W1 = (const float*)d_in[5];  const float* b1 = (const float*)d_in[6];
    const float* W2 = (const float*)d_in[7];  const float* b2 = (const float*)d_in[8];
    const float* W3 = (const float*)d_in[9];  const float* b3 = (const float*)d_in[10];
    const float* Wout = (const float*)d_in[11];
    const float* bout = (const float*)d_in[12];
    float* out = (float*)d_out;

    const int* src = eidx;
    const int* dst = eidx + NE;

    // ---- one-time CSR build ----
    k_init <<<(NG*DD + 255) / 256, 256>>>();
    k_deg  <<<(NE + 255) / 256, 256>>>(dst);
    k_scan1<<<SCAN_BLKS, 256>>>();
    k_scan2<<<1, 256>>>();
    k_scan3<<<SCAN_BLKS, 256>>>();
    k_fill <<<(NE + 255) / 256, 256>>>(src, dst);

    const int gemm_blocks = (NN + 3) / 4;           // 12500
    const int gath_blocks = (NN * 16 + 255) / 256;  // 3125

    // layer 0: aggregate-then-transform
    k_gather9<<<gath_blocks, 256>>>(x);
    k_gemm0f <<<gemm_blocks, 256>>>(W0, b0);
    // layers 1-3
    k_gemm64  <<<gemm_blocks, 256>>>(W1);
    k_gather64<false><<<gath_blocks, 256>>>(b1, batch);
    k_gemm64  <<<gemm_blocks, 256>>>(W2);
    k_gather64<false><<<gath_blocks, 256>>>(b2, batch);
    k_gemm64  <<<gemm_blocks, 256>>>(W3);
    k_gather64<true> <<<gath_blocks, 256>>>(b3, batch);

    k_out<<<(NG + 255) / 256, 256>>>(Wout, bout, out);
}